// round 5
// baseline (speedup 1.0000x reference)
#include <cuda_runtime.h>
#include <math.h>

// B=256 rows, C=2048 features, target groups of 4; output = last center's loss.
// Identity used: with c = mean of the matching rows and R = X X^T,
//   (x_i-c)·(x_j-c) = R_ij - u_i - u_j + cc,  u_i = mean_m R[m,i], cc = mean_m u_m
// so the GEMM runs on RAW inputs and centering/normalization moves to the reduce.
#define BDIM 256
#define CDIM 2048
#define KB 32                 // k's per smem stage
#define TOTSTG (CDIM / KB)    // 64 stages
#define NSLICE 14             // uneven split-K slices (4-5 stages each)
#define TILE 64
#define LDSR 34               // padded smem row stride: conflict-free LDS.64
#define EPSN 1e-12f

// Split-K partial Gram + compact partial diagonals (no zeroing needed: plain STG).
__device__ float d_Rp[NSLICE][BDIM * BDIM];   // 3.5 MB
__device__ float d_diagp[NSLICE][BDIM];

// Upper-triangle 64x64 tile pairs (it <= jt).
__device__ const int PIT[10] = {0, 0, 0, 0, 1, 1, 1, 2, 2, 3};
__device__ const int PJT[10] = {0, 1, 2, 3, 1, 2, 3, 2, 3, 3};

// Packed fp32x2 FMA (sm_10x): 2 fp32 FMA per issue slot.
__device__ __forceinline__ void ffma2(unsigned long long& d,
                                      unsigned long long a,
                                      unsigned long long b) {
    asm("fma.rn.f32x2 %0, %1, %2, %0;" : "+l"(d) : "l"(a), "l"(b));
}

// ---------------------------------------------------------------------------
// Kernel 1: split-K Gram GEMM on raw inputs, R = X X^T (upper-tri tile pairs).
// Grid (10, NSLICE). Double-buffered smem, register prefetch, fp32x2
// k-parity accumulators. Plain stores to the slice's private buffer
// (+ mirror for off-diagonal tiles, + compact diagonal for it==jt).
// ---------------------------------------------------------------------------
__global__ void __launch_bounds__(256) gemm_kernel(const float* __restrict__ x,
                                                   float* __restrict__ out) {
    __shared__ __align__(16) float As[2][TILE * LDSR];
    __shared__ __align__(16) float Bs[2][TILE * LDSR];

    const int tid = threadIdx.x;
    const int tx = tid & 15;
    const int ty = tid >> 4;
    const int it = PIT[blockIdx.x];
    const int jt = PJT[blockIdx.x];
    const int s  = blockIdx.y;
    const int s0 = (s * TOTSTG) / NSLICE;
    const int s1 = ((s + 1) * TOTSTG) / NSLICE;

    const int lr = tid >> 4;   // loader row-within-16
    const int lk = tid & 15;   // loader k-pair index

    // Zero the scalar output once per replay (runs before reduce's atomics).
    if (blockIdx.x == 0 && s == 0 && tid == 0) *out = 0.f;

    float2 pre[8];
    unsigned long long acc[16];
#pragma unroll
    for (int i = 0; i < 16; i++) acc[i] = 0ull;

    auto gload = [&](int st) {
        const int kb = st * KB + 2 * lk;
#pragma unroll
        for (int q = 0; q < 4; q++) {
            pre[q]     = *(const float2*)(x + (it * TILE + lr + 16 * q) * CDIM + kb);
            pre[4 + q] = *(const float2*)(x + (jt * TILE + lr + 16 * q) * CDIM + kb);
        }
    };
    auto sstore = [&](int b) {
#pragma unroll
        for (int q = 0; q < 4; q++) {
            *(float2*)(&As[b][(lr + 16 * q) * LDSR + 2 * lk]) = pre[q];
            *(float2*)(&Bs[b][(lr + 16 * q) * LDSR + 2 * lk]) = pre[4 + q];
        }
    };

    gload(s0);
    sstore(0);
    __syncthreads();

    for (int st = s0; st < s1; st++) {
        const int b = (st - s0) & 1;
        if (st + 1 < s1) gload(st + 1);  // prefetch next stage into regs

        const float* Ap = As[b];
        const float* Bp = Bs[b];
#pragma unroll
        for (int kp = 0; kp < KB / 2; kp++) {
            unsigned long long af[4], bf[4];
#pragma unroll
            for (int ii = 0; ii < 4; ii++)
                af[ii] = *(const unsigned long long*)(Ap + (ty + 16 * ii) * LDSR + 2 * kp);
#pragma unroll
            for (int jj = 0; jj < 4; jj++)
                bf[jj] = *(const unsigned long long*)(Bp + (tx + 16 * jj) * LDSR + 2 * kp);
#pragma unroll
            for (int ii = 0; ii < 4; ii++)
#pragma unroll
                for (int jj = 0; jj < 4; jj++)
                    ffma2(acc[ii * 4 + jj], af[ii], bf[jj]);
        }

        if (st + 1 < s1) sstore(b ^ 1);
        __syncthreads();
    }

    float* __restrict__ R = d_Rp[s];
#pragma unroll
    for (int ii = 0; ii < 4; ii++)
#pragma unroll
        for (int jj = 0; jj < 4; jj++) {
            const unsigned long long u = acc[ii * 4 + jj];
            const float r = __uint_as_float((unsigned)u) +
                            __uint_as_float((unsigned)(u >> 32));
            const int gi = it * TILE + ty + 16 * ii;
            const int gj = jt * TILE + tx + 16 * jj;
            R[gi * BDIM + gj] = r;
            if (it != jt) R[gj * BDIM + gi] = r;
            else if (tx == ty && ii == jj) d_diagp[s][gi] = r;  // compact diagonal
        }
}

// ---------------------------------------------------------------------------
// Kernel 2: centering + normalization corrections + masked min/max + sum.
// 32 blocks x 256 threads, one warp per row. Per block:
//   u[j]  = mean over center rows m of sum_s Rp[s][m,j]
//   cc    = mean over center rows of u
//   inv[j]= 1/max(sqrt(R_jj - 2u_j + cc), EPS)
//   angle = (R_ij - u_i - u_j + cc) * inv[i] * inv[j]
// ---------------------------------------------------------------------------
__global__ void __launch_bounds__(256) reduce_kernel(const int* __restrict__ tg,
                                                     float* __restrict__ out) {
    __shared__ int mlist[BDIM];
    __shared__ int mcount;
    __shared__ float su[BDIM];
    __shared__ float sinv[BDIM];

    const int tid = threadIdx.x;
    if (tid == 0) mcount = 0;
    __syncthreads();
    const int t_last = tg[BDIM - 4];       // targets[::4][-1]
    if (tg[tid] == t_last) {
        int p = atomicAdd(&mcount, 1);
        mlist[p] = tid;
    }
    __syncthreads();
    const int cnt = mcount;
    const float invc = 1.f / (float)cnt;

    // u[tid] = mean over center rows of full R column (coalesced, L2-hot).
    float u = 0.f;
    for (int m = 0; m < cnt; m++) {
        const int r = mlist[m];
#pragma unroll
        for (int s = 0; s < NSLICE; s++) u += d_Rp[s][r * BDIM + tid];
    }
    u *= invc;
    su[tid] = u;

    float dg = 0.f;
#pragma unroll
    for (int s = 0; s < NSLICE; s++) dg += d_diagp[s][tid];
    __syncthreads();

    float cc = 0.f;
    for (int m = 0; m < cnt; m++) cc += su[mlist[m]];
    cc *= invc;

    const float wii = dg - 2.f * u + cc;   // ||x_tid - c||^2
    sinv[tid] = 1.f / fmaxf(sqrtf(fmaxf(wii, 0.f)), EPSN);
    __syncthreads();

    const int row = blockIdx.x * 8 + (tid >> 5);
    const int lane = tid & 31;
    const int trow = tg[row];
    const float ui = su[row];
    const float invi = sinv[row];
    const float INF = __int_as_float(0x7f800000);

    float pos = INF;
    float neg = 0.f;
#pragma unroll
    for (int jj = 0; jj < 8; jj++) {
        const int j = lane + 32 * jj;
        float r = 0.f;
#pragma unroll
        for (int s = 0; s < NSLICE; s++) r += d_Rp[s][row * BDIM + j];
        const float w = r - ui - su[j] + cc;
        const float ang = w * invi * sinv[j];
        const bool same = (tg[j] == trow);
        pos = fminf(pos, same ? ang : INF);
        neg = fmaxf(neg, same ? 0.f : fmaxf(ang, 0.f));
    }
#pragma unroll
    for (int o = 16; o; o >>= 1) {
        pos = fminf(pos, __shfl_xor_sync(0xffffffffu, pos, o));
        neg = fmaxf(neg, __shfl_xor_sync(0xffffffffu, neg, o));
    }
    if (lane == 0) atomicAdd(out, expf(neg - pos) * (1.f / 448.f));
}

// ---------------------------------------------------------------------------
extern "C" void kernel_launch(void* const* d_in, const int* in_sizes, int n_in,
                              void* d_out, int out_size) {
    const float* x  = (const float*)d_in[0];   // inputs  [256, 2048] fp32
    const int*   tg = (const int*)d_in[1];     // targets [256] int32
    // d_in[2] (subs) is unused by the reference math.
    float* out = (float*)d_out;                // scalar fp32

    gemm_kernel<<<dim3(10, NSLICE), 256>>>(x, out);
    reduce_kernel<<<BDIM / 8, 256>>>(tg, out);
}

// round 6
// speedup vs baseline: 1.1082x; 1.1082x over previous
#include <cuda_runtime.h>
#include <math.h>

// B=256 rows, C=2048 features, target groups of 4; output = LAST center's loss.
// Identity: with c = mean of matching rows and R = X X^T,
//   (x_i-c)·(x_j-c) = R_ij - u_i - u_j + cc,  u_i = mean_m R[m,i], cc = mean_m u_m
// so the GEMM runs on RAW inputs; centering/normalization is O(B^2) epilogue.
#define BDIM 256
#define CDIM 2048
#define KB 32                  // k's per smem stage
#define TOTSTG (CDIM / KB)     // 64 stages
#define NSLICE 14              // uneven split-K slices (4-5 stages each)
#define NPAIR 10               // upper-triangle 64x64 tile pairs
#define NBLK (NPAIR * NSLICE)  // 140 blocks <= 148 SMs -> all resident
#define TILE 64
#define LDSR 34                // padded smem row stride: conflict-free LDS.64
#define EPSN 1e-12f

// Scratch (no allocations allowed).
__device__ float d_Rp[NSLICE][BDIM * BDIM];  // split-K partial Gram, 3.5 MB
__device__ float d_G[BDIM * BDIM];           // merged Gram, 256 KB
__device__ unsigned d_bar_arrive = 0;        // grid barrier state (monotonic gen)
__device__ unsigned d_bar_gen = 0;

__device__ const int PIT[NPAIR] = {0, 0, 0, 0, 1, 1, 1, 2, 2, 3};
__device__ const int PJT[NPAIR] = {0, 1, 2, 3, 1, 2, 3, 2, 3, 3};

// Packed fp32x2 FMA (sm_10x): 2 fp32 FMA per issue slot on the fma pipe.
__device__ __forceinline__ void ffma2(unsigned long long& d,
                                      unsigned long long a,
                                      unsigned long long b) {
    asm("fma.rn.f32x2 %0, %1, %2, %0;" : "+l"(d) : "l"(a), "l"(b));
}

// Sense-reversing software grid barrier. Safe: all NBLK CTAs are co-resident
// (1 CTA/SM). Generation counter is monotonic across graph replays.
__device__ __forceinline__ void grid_barrier() {
    __syncthreads();
    if (threadIdx.x == 0) {
        __threadfence();                              // release prior stores
        const unsigned g = atomicAdd(&d_bar_gen, 0);  // read gen BEFORE arriving
        if (atomicAdd(&d_bar_arrive, 1) == NBLK - 1) {
            atomicExch(&d_bar_arrive, 0);             // reset before gen bump
            __threadfence();
            atomicAdd(&d_bar_gen, 1);
        } else {
            while (atomicAdd(&d_bar_gen, 0) == g) {}
        }
        __threadfence();                              // acquire
    }
    __syncthreads();
}

// ---------------------------------------------------------------------------
// One persistent kernel, three phases separated by grid barriers:
//   1) split-K Gram GEMM on raw X into per-slice buffers (no atomics/zeroing)
//   2) all blocks merge the 14 slices into d_G (coalesced, L2-hot)
//   3) blocks 0..31: centering/normalization corrections + masked min/max + sum
// ---------------------------------------------------------------------------
__global__ void __launch_bounds__(256) fused_kernel(const float* __restrict__ x,
                                                    const int* __restrict__ tg,
                                                    float* __restrict__ out) {
    __shared__ __align__(16) float As[2][TILE * LDSR];
    __shared__ __align__(16) float Bs[2][TILE * LDSR];
    __shared__ int mlist[BDIM];
    __shared__ int mcount;
    __shared__ float su[BDIM];
    __shared__ float sinv[BDIM];

    const int tid = threadIdx.x;
    const int bid = blockIdx.x;

    // ======================= Phase 1: GEMM =======================
    {
        const int tx = tid & 15;
        const int ty = tid >> 4;
        const int pair = bid / NSLICE;
        const int s = bid % NSLICE;
        const int it = PIT[pair];
        const int jt = PJT[pair];
        const int s0 = (s * TOTSTG) / NSLICE;
        const int s1 = ((s + 1) * TOTSTG) / NSLICE;

        const int lr = tid >> 4;  // loader row-within-16
        const int lk = tid & 15;  // loader k-pair index

        float2 pre[8];
        unsigned long long acc[16];
#pragma unroll
        for (int i = 0; i < 16; i++) acc[i] = 0ull;

        auto gload = [&](int st) {
            const int kb = st * KB + 2 * lk;
#pragma unroll
            for (int q = 0; q < 4; q++) {
                pre[q]     = *(const float2*)(x + (it * TILE + lr + 16 * q) * CDIM + kb);
                pre[4 + q] = *(const float2*)(x + (jt * TILE + lr + 16 * q) * CDIM + kb);
            }
        };
        auto sstore = [&](int b) {
#pragma unroll
            for (int q = 0; q < 4; q++) {
                *(float2*)(&As[b][(lr + 16 * q) * LDSR + 2 * lk]) = pre[q];
                *(float2*)(&Bs[b][(lr + 16 * q) * LDSR + 2 * lk]) = pre[4 + q];
            }
        };

        gload(s0);
        sstore(0);
        __syncthreads();

        for (int st = s0; st < s1; st++) {
            const int b = (st - s0) & 1;
            if (st + 1 < s1) gload(st + 1);  // prefetch next stage into regs

            const float* Ap = As[b];
            const float* Bp = Bs[b];
#pragma unroll
            for (int kp = 0; kp < KB / 2; kp++) {
                unsigned long long af[4], bf[4];
#pragma unroll
                for (int ii = 0; ii < 4; ii++)
                    af[ii] = *(const unsigned long long*)(Ap + (ty + 16 * ii) * LDSR + 2 * kp);
#pragma unroll
                for (int jj = 0; jj < 4; jj++)
                    bf[jj] = *(const unsigned long long*)(Bp + (tx + 16 * jj) * LDSR + 2 * kp);
#pragma unroll
                for (int ii = 0; ii < 4; ii++)
#pragma unroll
                    for (int jj = 0; jj < 4; jj++)
                        ffma2(acc[ii * 4 + jj], af[ii], bf[jj]);
            }

            if (st + 1 < s1) sstore(b ^ 1);
            __syncthreads();
        }

        float* __restrict__ R = d_Rp[s];
#pragma unroll
        for (int ii = 0; ii < 4; ii++)
#pragma unroll
            for (int jj = 0; jj < 4; jj++) {
                const unsigned long long u = acc[ii * 4 + jj];
                const float r = __uint_as_float((unsigned)u) +
                                __uint_as_float((unsigned)(u >> 32));
                const int gi = it * TILE + ty + 16 * ii;
                const int gj = jt * TILE + tx + 16 * jj;
                R[gi * BDIM + gj] = r;
                if (it != jt) R[gj * BDIM + gi] = r;
            }
    }

    grid_barrier();

    // ======================= Phase 2: merge slices =======================
    for (int idx = bid * 256 + tid; idx < BDIM * BDIM; idx += NBLK * 256) {
        float v = 0.f;
#pragma unroll
        for (int s = 0; s < NSLICE; s++) v += d_Rp[s][idx];
        d_G[idx] = v;
    }
    if (bid == 0 && tid == 0) *out = 0.f;  // d_out is poisoned each replay

    grid_barrier();

    // ======================= Phase 3: reduce (blocks 0..31) ==============
    if (bid >= 32) return;

    if (tid == 0) mcount = 0;
    __syncthreads();
    const int t_last = tg[BDIM - 4];  // targets[::4][-1]
    if (tg[tid] == t_last) {
        int p = atomicAdd(&mcount, 1);
        mlist[p] = tid;
    }
    __syncthreads();
    const int cnt = mcount;
    const float invc = 1.f / (float)cnt;

    float u = 0.f;
    for (int m = 0; m < cnt; m++) u += d_G[mlist[m] * BDIM + tid];
    u *= invc;
    su[tid] = u;
    const float dg = d_G[tid * (BDIM + 1)];
    __syncthreads();

    float cc = 0.f;
    for (int m = 0; m < cnt; m++) cc += su[mlist[m]];
    cc *= invc;

    const float wii = dg - 2.f * u + cc;  // ||x_tid - c||^2
    sinv[tid] = 1.f / fmaxf(sqrtf(fmaxf(wii, 0.f)), EPSN);
    __syncthreads();

    const int row = bid * 8 + (tid >> 5);
    const int lane = tid & 31;
    const int trow = tg[row];
    const float ui = su[row];
    const float invi = sinv[row];
    const float INF = __int_as_float(0x7f800000);

    float pos = INF;
    float neg = 0.f;
#pragma unroll
    for (int jj = 0; jj < 8; jj++) {
        const int j = lane + 32 * jj;
        const float w = d_G[row * BDIM + j] - ui - su[j] + cc;
        const float ang = w * invi * sinv[j];
        const bool same = (tg[j] == trow);
        pos = fminf(pos, same ? ang : INF);
        neg = fmaxf(neg, same ? 0.f : fmaxf(ang, 0.f));
    }
#pragma unroll
    for (int o = 16; o; o >>= 1) {
        pos = fminf(pos, __shfl_xor_sync(0xffffffffu, pos, o));
        neg = fmaxf(neg, __shfl_xor_sync(0xffffffffu, neg, o));
    }
    if (lane == 0) atomicAdd(out, expf(neg - pos) * (1.f / 448.f));
}

// ---------------------------------------------------------------------------
extern "C" void kernel_launch(void* const* d_in, const int* in_sizes, int n_in,
                              void* d_out, int out_size) {
    const float* x  = (const float*)d_in[0];   // inputs  [256, 2048] fp32
    const int*   tg = (const int*)d_in[1];     // targets [256] int32
    // d_in[2] (subs) is unused by the reference math.
    float* out = (float*)d_out;                // scalar fp32

    fused_kernel<<<NBLK, 256>>>(x, tg, out);
}